// round 15
// baseline (speedup 1.0000x reference)
#include <cuda_runtime.h>
#include <math.h>

// Problem shape (fixed by setup_inputs)
#define B_ 4
#define S_ 4096
#define H_ 768
#define E_ 64

typedef long long ll;
typedef unsigned long long ull;

// ---------------------------------------------------------------------------
// Scratch (allocation-free per harness rules)
// ---------------------------------------------------------------------------
__device__ __align__(256) float g_q[(size_t)B_ * S_ * H_];
__device__ __align__(256) float g_k[(size_t)B_ * S_ * H_];
__device__ __align__(256) float g_v[(size_t)B_ * S_ * H_];
__device__ __align__(256) float g_scores[(size_t)B_ * S_ * S_];   // 256 MB
__device__ __align__(256) float g_colbias[B_ * S_];

// ---------------------------------------------------------------------------
// Packed fp32x2 FMA (Blackwell FFMA2; PTX-only pattern, confirmed working R14)
// ---------------------------------------------------------------------------
__device__ __forceinline__ void fma2(ull& c, ull a, ull b) {
    asm("fma.rn.f32x2 %0, %1, %2, %0;" : "+l"(c) : "l"(a), "l"(b));
}

// ---------------------------------------------------------------------------
// Column-bias prep: colbias[b][s] = (1-mask)*-10000 + (#entity hits at s)
// ---------------------------------------------------------------------------
__global__ void bias_init_kernel(const float* __restrict__ mask)
{
    int i = blockIdx.x * blockDim.x + threadIdx.x;
    if (i < B_ * S_) g_colbias[i] = (1.0f - mask[i]) * -10000.0f;
}
__global__ void bias_scatter_kernel(const int* __restrict__ epos)
{
    int i = threadIdx.x;
    if (i < B_ * E_) atomicAdd(&g_colbias[(i / E_) * S_ + epos[i]], 1.0f);
}

// ---------------------------------------------------------------------------
// Tiled FFMA2 SGEMM: C = A * op(B), 128x128 block, 8x8/thread, BK=8,
// double-buffered smem.
//   BT : B is NxK (NT) vs KxN (NN) row-major.
//   EPI=0: C=acc+aux[col]; EPI=1: C=acc*alpha+aux[col]; EPI=2: C=acc
// A stored DUPLICATED in smem ({a,a} pairs) so FFMA2 broadcast operands come
// straight from LDS.128 — no mov.b64 packing in the inner loop (R14: 22.9% alu).
// Bs group-padded (col' = col + (col>>3)*4, row len 196) => conflict-free reads.
// ---------------------------------------------------------------------------
constexpr int BM = 128, BN = 128, BK = 8, TM = 8, TN = 8;
constexpr int ASW = 2 * BM + 4;   // duplicated-A row length (260 floats, 16B-mult stride)
constexpr int BNP = 196;

__device__ __forceinline__ int bmap(int c) { return c + ((c >> 3) << 2); }

template <bool BT, int EPI>
__device__ __forceinline__
void sgemm_body(const float* __restrict__ A, const float* __restrict__ Bm,
                float* __restrict__ C,
                int K, int lda, int ldb, int ldc,
                const float* __restrict__ auxp, float alpha)
{
    __shared__ __align__(16) float As2[2][BK][ASW];
    __shared__ __align__(16) float Bs[2][BK][BNP];

    const int tid = threadIdx.x;
    const int tx = tid & 15;
    const int ty = tid >> 4;
    const int rowBase = blockIdx.y * BM;
    const int colBase = blockIdx.x * BN;

    const int arow = tid >> 1;
    const int acol = (tid & 1) * 4;
    int brow, bcol;
    if (BT) { brow = tid >> 1; bcol = (tid & 1) * 4; }
    else    { brow = tid >> 5; bcol = (tid & 31) * 4; }

    const float* Aptr = A + (ll)(rowBase + arow) * lda + acol;
    const float* Bptr = BT ? (Bm + (ll)(colBase + brow) * ldb + bcol)
                           : (Bm + (ll)brow * ldb + colBase + bcol);

    ull acc2[TM][TN / 2];
#pragma unroll
    for (int i = 0; i < TM; i++)
#pragma unroll
        for (int j = 0; j < TN / 2; j++) acc2[i][j] = 0ull;

    // ---- first tile -> buffer 0 ----
    float4 av = *reinterpret_cast<const float4*>(Aptr);
    float4 bv = *reinterpret_cast<const float4*>(Bptr);
    {
        const float a4[4] = {av.x, av.y, av.z, av.w};
#pragma unroll
        for (int c = 0; c < 4; c++)
            *reinterpret_cast<float2*>(&As2[0][acol + c][2 * arow]) =
                make_float2(a4[c], a4[c]);
    }
    if (BT) {
        const int bn = bmap(brow);
        Bs[0][bcol + 0][bn] = bv.x; Bs[0][bcol + 1][bn] = bv.y;
        Bs[0][bcol + 2][bn] = bv.z; Bs[0][bcol + 3][bn] = bv.w;
    } else {
        *reinterpret_cast<float4*>(&Bs[0][brow][bmap(bcol)]) = bv;
    }
    __syncthreads();

    int buf = 0;
    for (int kt = 0; kt < K; kt += BK) {
        const bool more = (kt + BK) < K;
        if (more) {
            av = *reinterpret_cast<const float4*>(Aptr + kt + BK);
            if (BT) bv = *reinterpret_cast<const float4*>(Bptr + kt + BK);
            else    bv = *reinterpret_cast<const float4*>(Bptr + (ll)(kt + BK) * ldb);
        }
#pragma unroll
        for (int kk = 0; kk < BK; kk++) {
            // A: 4 x LDS.128 of duplicated pairs -> 8 broadcast operands, 0 movs
            const ulonglong2* ap = reinterpret_cast<const ulonglong2*>(
                &As2[buf][kk][2 * (ty * TM)]);
            const ulonglong2 ua0 = ap[0];
            const ulonglong2 ua1 = ap[1];
            const ulonglong2 ua2 = ap[2];
            const ulonglong2 ua3 = ap[3];
            const ull a2[TM] = {ua0.x, ua0.y, ua1.x, ua1.y,
                                ua2.x, ua2.y, ua3.x, ua3.y};
            // B: 2 x LDS.128 -> 4 packed pair operands
            const ulonglong2* bp = reinterpret_cast<const ulonglong2*>(
                &Bs[buf][kk][tx * TN + tx * 4]);
            const ulonglong2 ub0 = bp[0];
            const ulonglong2 ub1 = bp[1];
            const ull b2[TN / 2] = {ub0.x, ub0.y, ub1.x, ub1.y};
#pragma unroll
            for (int i = 0; i < TM; i++)
#pragma unroll
                for (int j = 0; j < TN / 2; j++)
                    fma2(acc2[i][j], a2[i], b2[j]);
        }
        if (more) {
            const int nb = buf ^ 1;
            const float a4[4] = {av.x, av.y, av.z, av.w};
#pragma unroll
            for (int c = 0; c < 4; c++)
                *reinterpret_cast<float2*>(&As2[nb][acol + c][2 * arow]) =
                    make_float2(a4[c], a4[c]);
            if (BT) {
                const int bn = bmap(brow);
                Bs[nb][bcol + 0][bn] = bv.x; Bs[nb][bcol + 1][bn] = bv.y;
                Bs[nb][bcol + 2][bn] = bv.z; Bs[nb][bcol + 3][bn] = bv.w;
            } else {
                *reinterpret_cast<float4*>(&Bs[nb][brow][bmap(bcol)]) = bv;
            }
        }
        __syncthreads();
        buf ^= 1;
    }

    float auxv[TN];
    if (EPI < 2) {
#pragma unroll
        for (int j = 0; j < TN; j++) auxv[j] = auxp[colBase + tx * TN + j];
    }
#pragma unroll
    for (int i = 0; i < TM; i++) {
        float* cp = C + (ll)(rowBase + ty * TM + i) * ldc + colBase + tx * TN;
        float o[TN];
#pragma unroll
        for (int j = 0; j < TN; j++) {
            const ull p = acc2[i][j >> 1];
            float vv = (j & 1) ? __uint_as_float((unsigned)(p >> 32))
                               : __uint_as_float((unsigned)p);
            if (EPI == 0)      vv = vv + auxv[j];
            else if (EPI == 1) vv = vv * alpha + auxv[j];
            o[j] = vv;
        }
        *reinterpret_cast<float4*>(cp)     = make_float4(o[0], o[1], o[2], o[3]);
        *reinterpret_cast<float4*>(cp + 4) = make_float4(o[4], o[5], o[6], o[7]);
    }
}

// ---- wrappers ---------------------------------------------------------------
__global__ __launch_bounds__(256, 2)
void qkv_kernel(const float* __restrict__ hs,
                const float* __restrict__ Wq, const float* __restrict__ bq,
                const float* __restrict__ Wk, const float* __restrict__ bk,
                const float* __restrict__ Wv, const float* __restrict__ bv)
{
    const int z = blockIdx.z;
    const float* W    = (z == 0) ? Wq : (z == 1) ? Wk : Wv;
    const float* bias = (z == 0) ? bq : (z == 1) ? bk : bv;
    float* out        = (z == 0) ? g_q : (z == 1) ? g_k : g_v;
    sgemm_body<true, 0>(hs, W, out, H_, H_, H_, H_, bias, 1.0f);
}

__global__ __launch_bounds__(256, 2)
void scores_kernel(float alpha)
{
    const int bz = blockIdx.z;
    sgemm_body<true, 1>(g_q + (ll)bz * S_ * H_, g_k + (ll)bz * S_ * H_,
                        g_scores + (ll)bz * S_ * S_,
                        H_, H_, H_, S_, g_colbias + bz * S_, alpha);
}

__global__ __launch_bounds__(256, 2)
void pv_kernel(float* __restrict__ out)
{
    const int bz = blockIdx.z;
    sgemm_body<false, 2>(g_scores + (ll)bz * S_ * S_, g_v + (ll)bz * S_ * H_,
                         out + (ll)bz * S_ * H_,
                         S_, S_, H_, H_, nullptr, 1.0f);
}

// ---------------------------------------------------------------------------
// Row softmax over S_=4096 columns. One block per row, values in registers.
// ---------------------------------------------------------------------------
__global__ __launch_bounds__(256) void softmax_rows()
{
    const ll row = blockIdx.x;
    float4* p4 = reinterpret_cast<float4*>(g_scores + row * (ll)S_);
    const int t = threadIdx.x;
    const int lane = t & 31, w = t >> 5;

    float4 v[4];
    float m = -1e30f;
#pragma unroll
    for (int i = 0; i < 4; i++) {
        v[i] = p4[t + i * 256];
        m = fmaxf(m, fmaxf(fmaxf(v[i].x, v[i].y), fmaxf(v[i].z, v[i].w)));
    }

    __shared__ float sh[8];
    __shared__ float bres;
#pragma unroll
    for (int o = 16; o; o >>= 1) m = fmaxf(m, __shfl_xor_sync(0xffffffffu, m, o));
    if (!lane) sh[w] = m;
    __syncthreads();
    if (t == 0) {
        float mm = sh[0];
#pragma unroll
        for (int i = 1; i < 8; i++) mm = fmaxf(mm, sh[i]);
        bres = mm;
    }
    __syncthreads();
    m = bres;

    float s = 0.f;
#pragma unroll
    for (int i = 0; i < 4; i++) {
        v[i].x = __expf(v[i].x - m); v[i].y = __expf(v[i].y - m);
        v[i].z = __expf(v[i].z - m); v[i].w = __expf(v[i].w - m);
        s += (v[i].x + v[i].y) + (v[i].z + v[i].w);
    }
#pragma unroll
    for (int o = 16; o; o >>= 1) s += __shfl_xor_sync(0xffffffffu, s, o);
    if (!lane) sh[w] = s;
    __syncthreads();
    if (t == 0) {
        float ss = 0.f;
#pragma unroll
        for (int i = 0; i < 8; i++) ss += sh[i];
        bres = ss;
    }
    __syncthreads();
    const float inv = 1.0f / bres;
#pragma unroll
    for (int i = 0; i < 4; i++) {
        v[i].x *= inv; v[i].y *= inv; v[i].z *= inv; v[i].w *= inv;
        p4[t + i * 256] = v[i];
    }
}

// ---------------------------------------------------------------------------
extern "C" void kernel_launch(void* const* d_in, const int* in_sizes, int n_in,
                              void* d_out, int out_size)
{
    const float* hs   = (const float*)d_in[0];
    const float* mask = (const float*)d_in[1];
    const int*   epos = (const int*)d_in[2];
    const float* Wq   = (const float*)d_in[3];
    const float* bq   = (const float*)d_in[4];
    const float* Wk   = (const float*)d_in[5];
    const float* bk   = (const float*)d_in[6];
    const float* Wv   = (const float*)d_in[7];
    const float* bv   = (const float*)d_in[8];
    float* out = (float*)d_out;

    // 1) column bias
    bias_init_kernel<<<(B_ * S_ + 255) / 256, 256>>>(mask);
    bias_scatter_kernel<<<1, 256>>>(epos);

    // 2) QKV projections (fused NT gemm, bias epilogue)
    qkv_kernel<<<dim3(H_ / BN, (B_ * S_) / BM, 3), 256>>>(hs, Wq, bq, Wk, bk, Wv, bv);

    // 3) scores = (Q Kt)/sqrt(H) + colbias
    const float alpha = 1.0f / sqrtf((float)H_);
    scores_kernel<<<dim3(S_ / BN, S_ / BM, B_), 256>>>(alpha);

    // 4) row softmax (in-place fp32)
    softmax_rows<<<B_ * S_, 256>>>();

    // 5) context = P V -> d_out
    pv_kernel<<<dim3(H_ / BN, S_ / BM, B_), 256>>>(out);
}

// round 16
// speedup vs baseline: 1.1610x; 1.1610x over previous
#include <cuda_runtime.h>
#include <math.h>

// Problem shape (fixed by setup_inputs)
#define B_ 4
#define S_ 4096
#define H_ 768
#define E_ 64

typedef long long ll;
typedef unsigned long long ull;

// ---------------------------------------------------------------------------
// Scratch (allocation-free per harness rules)
// ---------------------------------------------------------------------------
__device__ __align__(256) float g_q[(size_t)B_ * S_ * H_];
__device__ __align__(256) float g_k[(size_t)B_ * S_ * H_];
__device__ __align__(256) float g_v[(size_t)B_ * S_ * H_];
__device__ __align__(256) float g_scores[(size_t)B_ * S_ * S_];   // 256 MB
__device__ __align__(256) float g_colbias[B_ * S_];

// ---------------------------------------------------------------------------
// Packed fp32x2 FMA (Blackwell FFMA2; PTX-only, confirmed working R14)
// ---------------------------------------------------------------------------
__device__ __forceinline__ void fma2(ull& c, ull a, ull b) {
    asm("fma.rn.f32x2 %0, %1, %2, %0;" : "+l"(c) : "l"(a), "l"(b));
}
__device__ __forceinline__ ull bcast2(float x) {
    ull r;
    asm("mov.b64 %0, {%1, %1};" : "=l"(r) : "f"(x));
    return r;
}

// ---------------------------------------------------------------------------
// Column-bias prep: colbias[b][s] = (1-mask)*-10000 + (#entity hits at s)
// ---------------------------------------------------------------------------
__global__ void bias_init_kernel(const float* __restrict__ mask)
{
    int i = blockIdx.x * blockDim.x + threadIdx.x;
    if (i < B_ * S_) g_colbias[i] = (1.0f - mask[i]) * -10000.0f;
}
__global__ void bias_scatter_kernel(const int* __restrict__ epos)
{
    int i = threadIdx.x;
    if (i < B_ * E_) atomicAdd(&g_colbias[(i / E_) * S_ + epos[i]], 1.0f);
}

// ---------------------------------------------------------------------------
// Tiled FFMA2 SGEMM: C = A * op(B), 128x128 block, BK=8, double-buffered.
// Thread tile 16x4, accumulators PACKED ALONG i (rows):
//   - A pair operands {A[2p],A[2p+1]} come free from LDS.128 of contiguous
//     rows (all lanes of a warp share ty => pure broadcast reads).
//   - Only TN=4 bcast movs per kk (half of R14's 8).
//   BT : B is NxK (NT) vs KxN (NN) row-major.
//   EPI=0: C=acc+aux[col]; EPI=1: C=acc*alpha+aux[col]; EPI=2: C=acc
// ---------------------------------------------------------------------------
constexpr int BM = 128, BN = 128, BK = 8, TM = 16, TN = 4;
constexpr int ASW = BM + 4;   // 132
constexpr int BSW = BN + 4;   // 132

template <bool BT, int EPI>
__device__ __forceinline__
void sgemm_body(const float* __restrict__ A, const float* __restrict__ Bm,
                float* __restrict__ C,
                int K, int lda, int ldb, int ldc,
                const float* __restrict__ auxp, float alpha)
{
    __shared__ __align__(16) float As[2][BK][ASW];
    __shared__ __align__(16) float Bs[2][BK][BSW];

    const int tid = threadIdx.x;
    const int tx = tid & 31;          // 32 col-groups of 4
    const int ty = tid >> 5;          // 8 row-groups of 16 (== warp id)
    const int rowBase = blockIdx.y * BM;
    const int colBase = blockIdx.x * BN;

    // global->smem load mapping: 128x8 tile, one float4 per thread
    const int arow = tid >> 1;
    const int acol = (tid & 1) * 4;
    int brow, bcol;
    if (BT) { brow = tid >> 1; bcol = (tid & 1) * 4; }
    else    { brow = tid >> 5; bcol = (tid & 31) * 4; }

    const float* Aptr = A + (ll)(rowBase + arow) * lda + acol;
    const float* Bptr = BT ? (Bm + (ll)(colBase + brow) * ldb + bcol)
                           : (Bm + (ll)brow * ldb + colBase + bcol);

    ull acc2[TM / 2][TN];   // packed {row 2p, row 2p+1} x col j
#pragma unroll
    for (int p = 0; p < TM / 2; p++)
#pragma unroll
        for (int j = 0; j < TN; j++) acc2[p][j] = 0ull;

    // ---- first tile -> buffer 0 ----
    float4 av = *reinterpret_cast<const float4*>(Aptr);
    float4 bv = *reinterpret_cast<const float4*>(Bptr);
    As[0][acol + 0][arow] = av.x; As[0][acol + 1][arow] = av.y;
    As[0][acol + 2][arow] = av.z; As[0][acol + 3][arow] = av.w;
    if (BT) {
        Bs[0][bcol + 0][brow] = bv.x; Bs[0][bcol + 1][brow] = bv.y;
        Bs[0][bcol + 2][brow] = bv.z; Bs[0][bcol + 3][brow] = bv.w;
    } else {
        *reinterpret_cast<float4*>(&Bs[0][brow][bcol]) = bv;
    }
    __syncthreads();

    int buf = 0;
    for (int kt = 0; kt < K; kt += BK) {
        const bool more = (kt + BK) < K;
        if (more) {
            av = *reinterpret_cast<const float4*>(Aptr + kt + BK);
            if (BT) bv = *reinterpret_cast<const float4*>(Bptr + kt + BK);
            else    bv = *reinterpret_cast<const float4*>(Bptr + (ll)(kt + BK) * ldb);
        }
#pragma unroll
        for (int kk = 0; kk < BK; kk++) {
            // A: 4 x LDS.128 broadcast (warp-uniform address), free i-pairs
            const ulonglong2* ap = reinterpret_cast<const ulonglong2*>(
                &As[buf][kk][ty * TM]);
            const ulonglong2 ua0 = ap[0];
            const ulonglong2 ua1 = ap[1];
            const ulonglong2 ua2 = ap[2];
            const ulonglong2 ua3 = ap[3];
            const ull a2[TM / 2] = {ua0.x, ua0.y, ua1.x, ua1.y,
                                    ua2.x, ua2.y, ua3.x, ua3.y};
            // B: 1 x LDS.128 + 4 broadcasts
            const float4 b4 = *reinterpret_cast<const float4*>(&Bs[buf][kk][tx * TN]);
            const ull b2[TN] = {bcast2(b4.x), bcast2(b4.y),
                                bcast2(b4.z), bcast2(b4.w)};
#pragma unroll
            for (int p = 0; p < TM / 2; p++)
#pragma unroll
                for (int j = 0; j < TN; j++)
                    fma2(acc2[p][j], a2[p], b2[j]);
        }
        if (more) {
            const int nb = buf ^ 1;
            As[nb][acol + 0][arow] = av.x; As[nb][acol + 1][arow] = av.y;
            As[nb][acol + 2][arow] = av.z; As[nb][acol + 3][arow] = av.w;
            if (BT) {
                Bs[nb][bcol + 0][brow] = bv.x; Bs[nb][bcol + 1][brow] = bv.y;
                Bs[nb][bcol + 2][brow] = bv.z; Bs[nb][bcol + 3][brow] = bv.w;
            } else {
                *reinterpret_cast<float4*>(&Bs[nb][brow][bcol]) = bv;
            }
        }
        __syncthreads();
        buf ^= 1;
    }

    // epilogue: each p covers rows (r0, r0+1); cols tx*4 .. tx*4+3
    float auxv[TN];
    if (EPI < 2) {
#pragma unroll
        for (int j = 0; j < TN; j++) auxv[j] = auxp[colBase + tx * TN + j];
    }
#pragma unroll
    for (int p = 0; p < TM / 2; p++) {
        const int r0 = rowBase + ty * TM + 2 * p;
        float o0[TN], o1[TN];
#pragma unroll
        for (int j = 0; j < TN; j++) {
            const ull pr = acc2[p][j];
            float lo = __uint_as_float((unsigned)pr);          // row r0
            float hi = __uint_as_float((unsigned)(pr >> 32));  // row r0+1
            if (EPI == 0)      { lo += auxv[j];               hi += auxv[j]; }
            else if (EPI == 1) { lo = lo * alpha + auxv[j];   hi = hi * alpha + auxv[j]; }
            o0[j] = lo; o1[j] = hi;
        }
        float* cp0 = C + (ll)r0 * ldc + colBase + tx * TN;
        float* cp1 = cp0 + ldc;
        *reinterpret_cast<float4*>(cp0) = make_float4(o0[0], o0[1], o0[2], o0[3]);
        *reinterpret_cast<float4*>(cp1) = make_float4(o1[0], o1[1], o1[2], o1[3]);
    }
}

// ---- wrappers ---------------------------------------------------------------
__global__ __launch_bounds__(256, 2)
void qkv_kernel(const float* __restrict__ hs,
                const float* __restrict__ Wq, const float* __restrict__ bq,
                const float* __restrict__ Wk, const float* __restrict__ bk,
                const float* __restrict__ Wv, const float* __restrict__ bv)
{
    const int z = blockIdx.z;
    const float* W    = (z == 0) ? Wq : (z == 1) ? Wk : Wv;
    const float* bias = (z == 0) ? bq : (z == 1) ? bk : bv;
    float* out        = (z == 0) ? g_q : (z == 1) ? g_k : g_v;
    sgemm_body<true, 0>(hs, W, out, H_, H_, H_, H_, bias, 1.0f);
}

__global__ __launch_bounds__(256, 2)
void scores_kernel(float alpha)
{
    const int bz = blockIdx.z;
    sgemm_body<true, 1>(g_q + (ll)bz * S_ * H_, g_k + (ll)bz * S_ * H_,
                        g_scores + (ll)bz * S_ * S_,
                        H_, H_, H_, S_, g_colbias + bz * S_, alpha);
}

__global__ __launch_bounds__(256, 2)
void pv_kernel(float* __restrict__ out)
{
    const int bz = blockIdx.z;
    sgemm_body<false, 2>(g_scores + (ll)bz * S_ * S_, g_v + (ll)bz * S_ * H_,
                         out + (ll)bz * S_ * H_,
                         S_, S_, H_, H_, nullptr, 1.0f);
}

// ---------------------------------------------------------------------------
// Row softmax over S_=4096 columns. One block per row, values in registers.
// ---------------------------------------------------------------------------
__global__ __launch_bounds__(256) void softmax_rows()
{
    const ll row = blockIdx.x;
    float4* p4 = reinterpret_cast<float4*>(g_scores + row * (ll)S_);
    const int t = threadIdx.x;
    const int lane = t & 31, w = t >> 5;

    float4 v[4];
    float m = -1e30f;
#pragma unroll
    for (int i = 0; i < 4; i++) {
        v[i] = p4[t + i * 256];
        m = fmaxf(m, fmaxf(fmaxf(v[i].x, v[i].y), fmaxf(v[i].z, v[i].w)));
    }

    __shared__ float sh[8];
    __shared__ float bres;
#pragma unroll
    for (int o = 16; o; o >>= 1) m = fmaxf(m, __shfl_xor_sync(0xffffffffu, m, o));
    if (!lane) sh[w] = m;
    __syncthreads();
    if (t == 0) {
        float mm = sh[0];
#pragma unroll
        for (int i = 1; i < 8; i++) mm = fmaxf(mm, sh[i]);
        bres = mm;
    }
    __syncthreads();
    m = bres;

    float s = 0.f;
#pragma unroll
    for (int i = 0; i < 4; i++) {
        v[i].x = __expf(v[i].x - m); v[i].y = __expf(v[i].y - m);
        v[i].z = __expf(v[i].z - m); v[i].w = __expf(v[i].w - m);
        s += (v[i].x + v[i].y) + (v[i].z + v[i].w);
    }
#pragma unroll
    for (int o = 16; o; o >>= 1) s += __shfl_xor_sync(0xffffffffu, s, o);
    if (!lane) sh[w] = s;
    __syncthreads();
    if (t == 0) {
        float ss = 0.f;
#pragma unroll
        for (int i = 0; i < 8; i++) ss += sh[i];
        bres = ss;
    }
    __syncthreads();
    const float inv = 1.0f / bres;
#pragma unroll
    for (int i = 0; i < 4; i++) {
        v[i].x *= inv; v[i].y *= inv; v[i].z *= inv; v[i].w *= inv;
        p4[t + i * 256] = v[i];
    }
}

// ---------------------------------------------------------------------------
extern "C" void kernel_launch(void* const* d_in, const int* in_sizes, int n_in,
                              void* d_out, int out_size)
{
    const float* hs   = (const float*)d_in[0];
    const float* mask = (const float*)d_in[1];
    const int*   epos = (const int*)d_in[2];
    const float* Wq   = (const float*)d_in[3];
    const float* bq   = (const float*)d_in[4];
    const float* Wk   = (const float*)d_in[5];
    const float* bk   = (const float*)d_in[6];
    const float* Wv   = (const float*)d_in[7];
    const float* bv   = (const float*)d_in[8];
    float* out = (float*)d_out;

    // 1) column bias
    bias_init_kernel<<<(B_ * S_ + 255) / 256, 256>>>(mask);
    bias_scatter_kernel<<<1, 256>>>(epos);

    // 2) QKV projections (fused NT gemm, bias epilogue)
    qkv_kernel<<<dim3(H_ / BN, (B_ * S_) / BM, 3), 256>>>(hs, Wq, bq, Wk, bk, Wv, bv);

    // 3) scores = (Q Kt)/sqrt(H) + colbias
    const float alpha = 1.0f / sqrtf((float)H_);
    scores_kernel<<<dim3(S_ / BN, S_ / BM, B_), 256>>>(alpha);

    // 4) row softmax (in-place fp32)
    softmax_rows<<<B_ * S_, 256>>>();

    // 5) context = P V -> d_out
    pv_kernel<<<dim3(H_ / BN, S_ / BM, B_), 256>>>(out);
}

// round 17
// speedup vs baseline: 1.2182x; 1.0492x over previous
#include <cuda_runtime.h>
#include <math.h>

// Problem shape (fixed by setup_inputs)
#define B_ 4
#define S_ 4096
#define H_ 768
#define E_ 64

typedef long long ll;
typedef unsigned long long ull;

// ---------------------------------------------------------------------------
// Scratch (allocation-free per harness rules)
// ---------------------------------------------------------------------------
__device__ __align__(256) float g_q[(size_t)B_ * S_ * H_];
__device__ __align__(256) float g_k[(size_t)B_ * S_ * H_];
__device__ __align__(256) float g_v[(size_t)B_ * S_ * H_];
__device__ __align__(256) float g_scores[(size_t)B_ * S_ * S_];   // 256 MB
__device__ __align__(256) float g_colbias[B_ * S_];

// ---------------------------------------------------------------------------
// Packed fp32x2 FMA (Blackwell FFMA2; PTX-only, confirmed working R14)
// ---------------------------------------------------------------------------
__device__ __forceinline__ void fma2(ull& c, ull a, ull b) {
    asm("fma.rn.f32x2 %0, %1, %2, %0;" : "+l"(c) : "l"(a), "l"(b));
}
__device__ __forceinline__ ull bcast2(float x) {
    ull r;
    asm("mov.b64 %0, {%1, %1};" : "=l"(r) : "f"(x));
    return r;
}

// ---------------------------------------------------------------------------
// Column-bias prep: colbias[b][s] = (1-mask)*-10000 + (#entity hits at s)
// ---------------------------------------------------------------------------
__global__ void bias_init_kernel(const float* __restrict__ mask)
{
    int i = blockIdx.x * blockDim.x + threadIdx.x;
    if (i < B_ * S_) g_colbias[i] = (1.0f - mask[i]) * -10000.0f;
}
__global__ void bias_scatter_kernel(const int* __restrict__ epos)
{
    int i = threadIdx.x;
    if (i < B_ * E_) atomicAdd(&g_colbias[(i / E_) * S_ + epos[i]], 1.0f);
}

// ---------------------------------------------------------------------------
// Tiled FFMA2 SGEMM: C = A * op(B), 128x128 block, BK=16, double-buffered.
// Thread tile 16x4, accumulators packed along i (R16 layout — lowest ALU mix):
//   A pairs {A[2p],A[2p+1]} free via broadcast LDS.128; 4 bcast movs for B.
// BK=16 halves barrier count vs BK=8 (R16 stall evidence: issue 51.9%).
//   BT : B is NxK (NT) vs KxN (NN) row-major.
//   EPI=0: C=acc+aux[col]; EPI=1: C=acc*alpha+aux[col]; EPI=2: C=acc
// ---------------------------------------------------------------------------
constexpr int BM = 128, BN = 128, BK = 16, TM = 16, TN = 4;
constexpr int ASW = BM + 4;   // 132
constexpr int BSW = BN + 4;   // 132

template <bool BT, int EPI>
__device__ __forceinline__
void sgemm_body(const float* __restrict__ A, const float* __restrict__ Bm,
                float* __restrict__ C,
                int K, int lda, int ldb, int ldc,
                const float* __restrict__ auxp, float alpha)
{
    __shared__ __align__(16) float As[2][BK][ASW];
    __shared__ __align__(16) float Bs[2][BK][BSW];

    const int tid = threadIdx.x;
    const int tx = tid & 31;          // 32 col-groups of 4
    const int ty = tid >> 5;          // 8 row-groups of 16 (== warp id)
    const int rowBase = blockIdx.y * BM;
    const int colBase = blockIdx.x * BN;

    // global->smem mapping: 128x16 tile = 512 float4, 2 per thread
    // u = tid + 256*r : row = u>>2 (0..127), kchunk = (u&3)*4 (0..12)
    const int ar0 = tid >> 2, ac0 = (tid & 3) * 4;
    const int ar1 = (tid + 256) >> 2, ac1 = ((tid + 256) & 3) * 4;
    // B mapping (NN): 16x128 tile: brow = u>>5 (0..15), bcol = (u&31)*4
    const int br0 = tid >> 5, bc0 = (tid & 31) * 4;
    const int br1 = (tid + 256) >> 5, bc1 = ((tid + 256) & 31) * 4;

    const float* AptrBase = A + (ll)rowBase * lda;
    const float* BptrBase = BT ? (Bm + (ll)colBase * ldb) : (Bm + colBase);

    ull acc2[TM / 2][TN];
#pragma unroll
    for (int p = 0; p < TM / 2; p++)
#pragma unroll
        for (int j = 0; j < TN; j++) acc2[p][j] = 0ull;

    float4 av0, av1, bv0, bv1;
    // ---- first tile loads ----
    av0 = *reinterpret_cast<const float4*>(AptrBase + (ll)ar0 * lda + ac0);
    av1 = *reinterpret_cast<const float4*>(AptrBase + (ll)ar1 * lda + ac1);
    if (BT) {
        bv0 = *reinterpret_cast<const float4*>(BptrBase + (ll)ar0 * ldb + ac0);
        bv1 = *reinterpret_cast<const float4*>(BptrBase + (ll)ar1 * ldb + ac1);
    } else {
        bv0 = *reinterpret_cast<const float4*>(BptrBase + (ll)br0 * ldb + bc0);
        bv1 = *reinterpret_cast<const float4*>(BptrBase + (ll)br1 * ldb + bc1);
    }
    // store to buffer 0 (transposed for A and BT-B; direct for NN-B)
    {
        As[0][ac0 + 0][ar0] = av0.x; As[0][ac0 + 1][ar0] = av0.y;
        As[0][ac0 + 2][ar0] = av0.z; As[0][ac0 + 3][ar0] = av0.w;
        As[0][ac1 + 0][ar1] = av1.x; As[0][ac1 + 1][ar1] = av1.y;
        As[0][ac1 + 2][ar1] = av1.z; As[0][ac1 + 3][ar1] = av1.w;
        if (BT) {
            Bs[0][ac0 + 0][ar0] = bv0.x; Bs[0][ac0 + 1][ar0] = bv0.y;
            Bs[0][ac0 + 2][ar0] = bv0.z; Bs[0][ac0 + 3][ar0] = bv0.w;
            Bs[0][ac1 + 0][ar1] = bv1.x; Bs[0][ac1 + 1][ar1] = bv1.y;
            Bs[0][ac1 + 2][ar1] = bv1.z; Bs[0][ac1 + 3][ar1] = bv1.w;
        } else {
            *reinterpret_cast<float4*>(&Bs[0][br0][bc0]) = bv0;
            *reinterpret_cast<float4*>(&Bs[0][br1][bc1]) = bv1;
        }
    }
    __syncthreads();

    int buf = 0;
    for (int kt = 0; kt < K; kt += BK) {
        const bool more = (kt + BK) < K;
        if (more) {
            const int kn = kt + BK;
            av0 = *reinterpret_cast<const float4*>(AptrBase + (ll)ar0 * lda + kn + ac0);
            av1 = *reinterpret_cast<const float4*>(AptrBase + (ll)ar1 * lda + kn + ac1);
            if (BT) {
                bv0 = *reinterpret_cast<const float4*>(BptrBase + (ll)ar0 * ldb + kn + ac0);
                bv1 = *reinterpret_cast<const float4*>(BptrBase + (ll)ar1 * ldb + kn + ac1);
            } else {
                bv0 = *reinterpret_cast<const float4*>(BptrBase + (ll)(kn + br0) * ldb + bc0);
                bv1 = *reinterpret_cast<const float4*>(BptrBase + (ll)(kn + br1) * ldb + bc1);
            }
        }
#pragma unroll
        for (int kk = 0; kk < BK; kk++) {
            const ulonglong2* ap = reinterpret_cast<const ulonglong2*>(
                &As[buf][kk][ty * TM]);
            const ulonglong2 ua0 = ap[0];
            const ulonglong2 ua1 = ap[1];
            const ulonglong2 ua2 = ap[2];
            const ulonglong2 ua3 = ap[3];
            const ull a2[TM / 2] = {ua0.x, ua0.y, ua1.x, ua1.y,
                                    ua2.x, ua2.y, ua3.x, ua3.y};
            const float4 b4 = *reinterpret_cast<const float4*>(&Bs[buf][kk][tx * TN]);
            const ull b2[TN] = {bcast2(b4.x), bcast2(b4.y),
                                bcast2(b4.z), bcast2(b4.w)};
#pragma unroll
            for (int p = 0; p < TM / 2; p++)
#pragma unroll
                for (int j = 0; j < TN; j++)
                    fma2(acc2[p][j], a2[p], b2[j]);
        }
        if (more) {
            const int nb = buf ^ 1;
            As[nb][ac0 + 0][ar0] = av0.x; As[nb][ac0 + 1][ar0] = av0.y;
            As[nb][ac0 + 2][ar0] = av0.z; As[nb][ac0 + 3][ar0] = av0.w;
            As[nb][ac1 + 0][ar1] = av1.x; As[nb][ac1 + 1][ar1] = av1.y;
            As[nb][ac1 + 2][ar1] = av1.z; As[nb][ac1 + 3][ar1] = av1.w;
            if (BT) {
                Bs[nb][ac0 + 0][ar0] = bv0.x; Bs[nb][ac0 + 1][ar0] = bv0.y;
                Bs[nb][ac0 + 2][ar0] = bv0.z; Bs[nb][ac0 + 3][ar0] = bv0.w;
                Bs[nb][ac1 + 0][ar1] = bv1.x; Bs[nb][ac1 + 1][ar1] = bv1.y;
                Bs[nb][ac1 + 2][ar1] = bv1.z; Bs[nb][ac1 + 3][ar1] = bv1.w;
            } else {
                *reinterpret_cast<float4*>(&Bs[nb][br0][bc0]) = bv0;
                *reinterpret_cast<float4*>(&Bs[nb][br1][bc1]) = bv1;
            }
        }
        __syncthreads();
        buf ^= 1;
    }

    // epilogue: each p covers rows (r0, r0+1); cols tx*4 .. tx*4+3
    float auxv[TN];
    if (EPI < 2) {
#pragma unroll
        for (int j = 0; j < TN; j++) auxv[j] = auxp[colBase + tx * TN + j];
    }
#pragma unroll
    for (int p = 0; p < TM / 2; p++) {
        const int r0 = rowBase + ty * TM + 2 * p;
        float o0[TN], o1[TN];
#pragma unroll
        for (int j = 0; j < TN; j++) {
            const ull pr = acc2[p][j];
            float lo = __uint_as_float((unsigned)pr);
            float hi = __uint_as_float((unsigned)(pr >> 32));
            if (EPI == 0)      { lo += auxv[j];             hi += auxv[j]; }
            else if (EPI == 1) { lo = lo * alpha + auxv[j]; hi = hi * alpha + auxv[j]; }
            o0[j] = lo; o1[j] = hi;
        }
        float* cp0 = C + (ll)r0 * ldc + colBase + tx * TN;
        float* cp1 = cp0 + ldc;
        *reinterpret_cast<float4*>(cp0) = make_float4(o0[0], o0[1], o0[2], o0[3]);
        *reinterpret_cast<float4*>(cp1) = make_float4(o1[0], o1[1], o1[2], o1[3]);
    }
}

// ---- wrappers ---------------------------------------------------------------
__global__ __launch_bounds__(256, 2)
void qkv_kernel(const float* __restrict__ hs,
                const float* __restrict__ Wq, const float* __restrict__ bq,
                const float* __restrict__ Wk, const float* __restrict__ bk,
                const float* __restrict__ Wv, const float* __restrict__ bv)
{
    const int z = blockIdx.z;
    const float* W    = (z == 0) ? Wq : (z == 1) ? Wk : Wv;
    const float* bias = (z == 0) ? bq : (z == 1) ? bk : bv;
    float* out        = (z == 0) ? g_q : (z == 1) ? g_k : g_v;
    sgemm_body<true, 0>(hs, W, out, H_, H_, H_, H_, bias, 1.0f);
}

__global__ __launch_bounds__(256, 2)
void scores_kernel(float alpha)
{
    const int bz = blockIdx.z;
    sgemm_body<true, 1>(g_q + (ll)bz * S_ * H_, g_k + (ll)bz * S_ * H_,
                        g_scores + (ll)bz * S_ * S_,
                        H_, H_, H_, S_, g_colbias + bz * S_, alpha);
}

__global__ __launch_bounds__(256, 2)
void pv_kernel(float* __restrict__ out)
{
    const int bz = blockIdx.z;
    sgemm_body<false, 2>(g_scores + (ll)bz * S_ * S_, g_v + (ll)bz * S_ * H_,
                         out + (ll)bz * S_ * H_,
                         S_, S_, H_, H_, nullptr, 1.0f);
}

// ---------------------------------------------------------------------------
// Row softmax over S_=4096 columns. One block per row, values in registers.
// ---------------------------------------------------------------------------
__global__ __launch_bounds__(256) void softmax_rows()
{
    const ll row = blockIdx.x;
    float4* p4 = reinterpret_cast<float4*>(g_scores + row * (ll)S_);
    const int t = threadIdx.x;
    const int lane = t & 31, w = t >> 5;

    float4 v[4];
    float m = -1e30f;
#pragma unroll
    for (int i = 0; i < 4; i++) {
        v[i] = p4[t + i * 256];
        m = fmaxf(m, fmaxf(fmaxf(v[i].x, v[i].y), fmaxf(v[i].z, v[i].w)));
    }

    __shared__ float sh[8];
    __shared__ float bres;
#pragma unroll
    for (int o = 16; o; o >>= 1) m = fmaxf(m, __shfl_xor_sync(0xffffffffu, m, o));
    if (!lane) sh[w] = m;
    __syncthreads();
    if (t == 0) {
        float mm = sh[0];
#pragma unroll
        for (int i = 1; i < 8; i++) mm = fmaxf(mm, sh[i]);
        bres = mm;
    }
    __syncthreads();
    m = bres;

    float s = 0.f;
#pragma unroll
    for (int i = 0; i < 4; i++) {
        v[i].x = __expf(v[i].x - m); v[i].y = __expf(v[i].y - m);
        v[i].z = __expf(v[i].z - m); v[i].w = __expf(v[i].w - m);
        s += (v[i].x + v[i].y) + (v[i].z + v[i].w);
    }
#pragma unroll
    for (int o = 16; o; o >>= 1) s += __shfl_xor_sync(0xffffffffu, s, o);
    if (!lane) sh[w] = s;
    __syncthreads();
    if (t == 0) {
        float ss = 0.f;
#pragma unroll
        for (int i = 0; i < 8; i++) ss += sh[i];
        bres = ss;
    }
    __syncthreads();
    const float inv = 1.0f / bres;
#pragma unroll
    for (int i = 0; i < 4; i++) {
        v[i].x *= inv; v[i].y *= inv; v[i].z *= inv; v[i].w *= inv;
        p4[t + i * 256] = v[i];
    }
}

// ---------------------------------------------------------------------------
extern "C" void kernel_launch(void* const* d_in, const int* in_sizes, int n_in,
                              void* d_out, int out_size)
{
    const float* hs   = (const float*)d_in[0];
    const float* mask = (const float*)d_in[1];
    const int*   epos = (const int*)d_in[2];
    const float* Wq   = (const float*)d_in[3];
    const float* bq   = (const float*)d_in[4];
    const float* Wk   = (const float*)d_in[5];
    const float* bk   = (const float*)d_in[6];
    const float* Wv   = (const float*)d_in[7];
    const float* bv   = (const float*)d_in[8];
    float* out = (float*)d_out;

    // 1) column bias
    bias_init_kernel<<<(B_ * S_ + 255) / 256, 256>>>(mask);
    bias_scatter_kernel<<<1, 256>>>(epos);

    // 2) QKV projections (fused NT gemm, bias epilogue)
    qkv_kernel<<<dim3(H_ / BN, (B_ * S_) / BM, 3), 256>>>(hs, Wq, bq, Wk, bk, Wv, bv);

    // 3) scores = (Q Kt)/sqrt(H) + colbias
    const float alpha = 1.0f / sqrtf((float)H_);
    scores_kernel<<<dim3(S_ / BN, S_ / BM, B_), 256>>>(alpha);

    // 4) row softmax (in-place fp32)
    softmax_rows<<<B_ * S_, 256>>>();

    // 5) context = P V -> d_out
    pv_kernel<<<dim3(H_ / BN, S_ / BM, B_), 256>>>(out);
}